// round 2
// baseline (speedup 1.0000x reference)
#include <cuda_runtime.h>
#include <cstdint>

#define B_N   32
#define CIN   256
#define HW    3136
#define HW4   784
#define PX    100352          // B_N*HW
#define CO1   128
#define CO2   32
#define N_OUT (32*288*3136)

// ---------------- scratch (device globals; no allocations) ----------------
__device__ float    g_w1q[CIN], g_b1q[CIN];
__device__ float    g_bf[CO1], g_sw1[CO1], g_bfq[CO1], g_comb1[CO1];
__device__ int      g_wq1[CO1*64];          // int8 packed [oc][ci/4]
__device__ float    g_sw2[CO2], g_comb2[CO2];
__device__ int      g_wq2[CO2*288];         // [oc][tap*32 + ci/4]
__device__ unsigned g_max1, g_max2, g_maxb, g_maxy;
__device__ float    g_sa1, g_sa2, g_sout;
__device__ int      g_x1q32[PX*64];         // x1 codes NHWC packed
__device__ float    g_x2[PX*CO1];           // conv1 out fp32 NHWC
__device__ int      g_x2q32[PX*32];         // x2 codes NHWC packed

// ---------------- helpers ----------------
__device__ __forceinline__ float warpMax(float v) {
    #pragma unroll
    for (int o = 16; o; o >>= 1) v = fmaxf(v, __shfl_xor_sync(0xffffffffu, v, o));
    return v;
}
__device__ __forceinline__ float blockReduceMax(float v) {
    __shared__ float sm[8];
    float w = warpMax(v);
    if ((threadIdx.x & 31) == 0) sm[threadIdx.x >> 5] = w;
    __syncthreads();
    float r = (threadIdx.x < (blockDim.x >> 5)) ? sm[threadIdx.x] : 0.0f;
    r = warpMax(r);
    __syncthreads();
    return r;  // valid in warp 0
}
__device__ __forceinline__ float qclipf(float q, float lo, float hi) {
    return fminf(fmaxf(q, lo), hi);
}

// ---------------- K0: weight prep ----------------
__global__ void k_prep(const float* __restrict__ g1, const float* __restrict__ be1,
                       const float* __restrict__ m1, const float* __restrict__ v1,
                       const float* __restrict__ s_in_p, const float* __restrict__ w1c,
                       const float* __restrict__ g2, const float* __restrict__ be2,
                       const float* __restrict__ m2, const float* __restrict__ v2,
                       const float* __restrict__ w2c)
{
    int t = threadIdx.x;
    if (blockIdx.x == 0) {
        if (t == 0) { g_max1 = 0u; g_max2 = 0u; g_maxb = 0u; g_maxy = 0u; }
        float w1 = g1[t] / sqrtf(v1[t] + 1e-5f);
        float b1 = be1[t] - m1[t] * w1;
        float bm = blockReduceMax(fabsf(w1));
        __shared__ float s_sbn;
        if (t == 0) s_sbn = bm / 127.0f + 1e-8f;
        __syncthreads();
        float sbn = s_sbn;
        float c = qclipf(rintf(w1 / sbn), -128.0f, 127.0f);
        g_w1q[t] = c * sbn;
        float sc = s_in_p[0] * sbn;
        g_b1q[t] = rintf(b1 / sc) * sc;
    } else if (blockIdx.x == 1) {
        if (t < CO1) {
            float tt = g2[t] / sqrtf(v2[t] + 1e-5f);
            const float* wr = w1c + t * CIN;
            float mx = 0.0f;
            for (int c = 0; c < CIN; c++) mx = fmaxf(mx, fabsf(wr[c] * tt));
            float s = mx / 127.0f + 1e-8f;
            g_sw1[t] = s;
            g_bf[t]  = be2[t] - m2[t] * tt;
            for (int cw = 0; cw < 64; cw++) {
                unsigned word = 0;
                #pragma unroll
                for (int j = 0; j < 4; j++) {
                    float wf = wr[cw * 4 + j] * tt;
                    int qi = (int)qclipf(rintf(wf / s), -128.0f, 127.0f);
                    word |= ((unsigned)(qi & 0xff)) << (8 * j);
                }
                g_wq1[t * 64 + cw] = (int)word;
            }
        }
    } else {
        if (t < CO2) {
            const float* wr = w2c + t * 1152;   // [128 ci][3][3]
            float mx = 0.0f;
            for (int k = 0; k < 1152; k++) mx = fmaxf(mx, fabsf(wr[k]));
            float s = mx / 127.0f + 1e-8f;
            g_sw2[t] = s;
            for (int tap = 0; tap < 9; tap++)
                for (int cw = 0; cw < 32; cw++) {
                    unsigned word = 0;
                    #pragma unroll
                    for (int j = 0; j < 4; j++) {
                        int qi = (int)qclipf(rintf(wr[(cw * 4 + j) * 9 + tap] / s),
                                             -128.0f, 127.0f);
                        word |= ((unsigned)(qi & 0xff)) << (8 * j);
                    }
                    g_wq2[t * 288 + tap * 32 + cw] = (int)word;
                }
        }
    }
}

// ---------------- K1: max relu(bn1(batch)) and max|batch| ----------------
__global__ void k_max1(const float4* __restrict__ batch4)
{
    const int n4 = PX * CIN / 4;
    float m1 = 0.0f, mb = 0.0f;
    for (int i = blockIdx.x * blockDim.x + threadIdx.x; i < n4;
         i += gridDim.x * blockDim.x) {
        int c = (i / HW4) % CIN;
        float w = g_w1q[c], b = g_b1q[c];
        float4 v = batch4[i];
        m1 = fmaxf(m1, fmaxf(fmaf(v.x, w, b), 0.0f));
        m1 = fmaxf(m1, fmaxf(fmaf(v.y, w, b), 0.0f));
        m1 = fmaxf(m1, fmaxf(fmaf(v.z, w, b), 0.0f));
        m1 = fmaxf(m1, fmaxf(fmaf(v.w, w, b), 0.0f));
        mb = fmaxf(mb, fmaxf(fmaxf(fabsf(v.x), fabsf(v.y)),
                             fmaxf(fabsf(v.z), fabsf(v.w))));
    }
    float r1 = blockReduceMax(m1);
    if (threadIdx.x == 0) atomicMax(&g_max1, __float_as_uint(r1));
    float rb = blockReduceMax(mb);
    if (threadIdx.x == 0) atomicMax(&g_maxb, __float_as_uint(rb));
}

// ---------------- K2: s_a1, bfq, comb1 ----------------
__global__ void k_scales1()
{
    float s = __uint_as_float(g_max1) / 127.0f + 1e-8f;
    int t = threadIdx.x;
    if (t == 0) g_sa1 = s;
    if (t < CO1) {
        float sc = s * g_sw1[t];
        g_comb1[t] = sc;
        g_bfq[t]   = rintf(g_bf[t] / sc) * sc;
    }
}

// ---------------- K3: bn1 -> quantize -> NCHW->NHWC int8 ----------------
__global__ void k_quant1(const float* __restrict__ batch)
{
    __shared__ unsigned char sm8[64 * 264];
    int t = threadIdx.x;
    int p0 = blockIdx.x * 64;
    int b = p0 / HW, s0 = p0 % HW;
    float inv = 1.0f / g_sa1;
    const float4* bp = (const float4*)batch;
    #pragma unroll
    for (int i = 0; i < 16; i++) {
        int lin = t + 256 * i;                 // 4096 float4 groups
        int g = lin & 15, ci = lin >> 4;
        float4 v = bp[(b * CIN + ci) * HW4 + s0 / 4 + g];
        float w = g_w1q[ci], bb = g_b1q[ci];
        int base = (4 * g) * 264 + ci;
        float x0 = fmaxf(fmaf(v.x, w, bb), 0.0f);
        float x1 = fmaxf(fmaf(v.y, w, bb), 0.0f);
        float x2 = fmaxf(fmaf(v.z, w, bb), 0.0f);
        float x3 = fmaxf(fmaf(v.w, w, bb), 0.0f);
        sm8[base + 0 * 264] = (unsigned char)(int)qclipf(rintf(x0 * inv), 0.0f, 127.0f);
        sm8[base + 1 * 264] = (unsigned char)(int)qclipf(rintf(x1 * inv), 0.0f, 127.0f);
        sm8[base + 2 * 264] = (unsigned char)(int)qclipf(rintf(x2 * inv), 0.0f, 127.0f);
        sm8[base + 3 * 264] = (unsigned char)(int)qclipf(rintf(x3 * inv), 0.0f, 127.0f);
    }
    __syncthreads();
    const int* smw = (const int*)sm8;
    #pragma unroll
    for (int i = 0; i < 16; i++) {
        int lin = t + 256 * i;                 // 4096 words
        int cw = lin & 63, p = lin >> 6;
        g_x1q32[(p0 + p) * 64 + cw] = smw[p * 66 + cw];
    }
}

// ---------------- K4: conv1 1x1 int8 GEMM (128px x 128oc, K=256) ----------------
__global__ void k_conv1()
{
    extern __shared__ int smem[];
    int* Ws = smem;                    // [64 k][132]
    int* Bs = smem + 64 * 132;         // [128 px][65]
    float* sc1 = (float*)(Bs + 128 * 65);
    float* sb1 = sc1 + 128;
    int t = threadIdx.x;
    int p0 = blockIdx.x * 128;
    #pragma unroll
    for (int i = 0; i < 32; i++) {
        int lin = t + 256 * i;
        int oc = lin >> 6, k = lin & 63;
        Ws[k * 132 + oc] = g_wq1[lin];
    }
    #pragma unroll
    for (int i = 0; i < 32; i++) {
        int lin = t + 256 * i;
        Bs[(lin >> 6) * 65 + (lin & 63)] = g_x1q32[p0 * 64 + lin];
    }
    if (t < 128) { sc1[t] = g_comb1[t]; sb1[t] = g_bfq[t]; }
    __syncthreads();

    int tx = t & 15, ty = t >> 4;
    int acc[64];
    #pragma unroll
    for (int i = 0; i < 64; i++) acc[i] = 0;
    const int* wp = Ws + 8 * tx;
    const int* bp = Bs + ty * 8 * 65;
    #pragma unroll 4
    for (int k = 0; k < 64; k++) {
        int4 a0 = *(const int4*)(wp + k * 132);
        int4 a1 = *(const int4*)(wp + k * 132 + 4);
        int a[8] = {a0.x, a0.y, a0.z, a0.w, a1.x, a1.y, a1.z, a1.w};
        #pragma unroll
        for (int j = 0; j < 8; j++) {
            int bv = bp[j * 65 + k];
            #pragma unroll
            for (int i2 = 0; i2 < 8; i2++)
                acc[j * 8 + i2] = __dp4a(bv, a[i2], acc[j * 8 + i2]);
        }
    }
    float m = 0.0f;
    #pragma unroll
    for (int j = 0; j < 8; j++) {
        int px = p0 + ty * 8 + j;
        float vals[8];
        #pragma unroll
        for (int i2 = 0; i2 < 8; i2++) {
            int oc = tx * 8 + i2;
            float v = fmaxf(fmaf((float)acc[j * 8 + i2], sc1[oc], sb1[oc]), 0.0f);
            vals[i2] = v; m = fmaxf(m, v);
        }
        float4* op = (float4*)&g_x2[px * 128 + tx * 8];
        op[0] = make_float4(vals[0], vals[1], vals[2], vals[3]);
        op[1] = make_float4(vals[4], vals[5], vals[6], vals[7]);
    }
    float bm = blockReduceMax(m);
    if (t == 0) atomicMax(&g_max2, __float_as_uint(bm));
}

// ---------------- K5: s_a2, comb2 ----------------
__global__ void k_scales2()
{
    float s = __uint_as_float(g_max2) / 127.0f + 1e-8f;
    if (threadIdx.x == 0) g_sa2 = s;
    if (threadIdx.x < CO2) g_comb2[threadIdx.x] = s * g_sw2[threadIdx.x];
}

// ---------------- K6: quantize x2 -> int8 NHWC packed ----------------
__global__ void k_quant2()
{
    const int n = PX * 32;
    float inv = 1.0f / g_sa2;
    const float4* xp = (const float4*)g_x2;
    for (int i = blockIdx.x * blockDim.x + threadIdx.x; i < n;
         i += gridDim.x * blockDim.x) {
        float4 v = xp[i];
        int q0 = (int)qclipf(rintf(v.x * inv), 0.0f, 127.0f);
        int q1 = (int)qclipf(rintf(v.y * inv), 0.0f, 127.0f);
        int q2 = (int)qclipf(rintf(v.z * inv), 0.0f, 127.0f);
        int q3 = (int)qclipf(rintf(v.w * inv), 0.0f, 127.0f);
        g_x2q32[i] = q0 | (q1 << 8) | (q2 << 16) | (q3 << 24);
    }
}

// ---------------- K7: conv2 3x3 int8, one (b,h) row per block ----------------
__global__ void k_conv2(float* __restrict__ out)
{
    extern __shared__ int smem[];
    int*   Xs   = smem;                    // [3 rows][58 cols] cells of 36 words
    int*   Wsm  = smem + 3 * 58 * 36;      // [32 oc][292]
    float* scmb = (float*)(Wsm + 32 * 292);
    int t = threadIdx.x;
    int h = blockIdx.x, b = blockIdx.y;

    for (int lin = t; lin < 3 * 58 * 32; lin += 256) {
        int row = lin / (58 * 32);
        int rem = lin % (58 * 32);
        int col = rem >> 5, kw = rem & 31;
        int hh = h + row - 1;
        int val = 0;
        if (col >= 1 && col <= 56 && hh >= 0 && hh <= 55)
            val = g_x2q32[((b * HW) + hh * 56 + (col - 1)) * 32 + kw];
        Xs[(row * 58 + col) * 36 + kw] = val;
    }
    for (int lin = t; lin < 32 * 288; lin += 256) {
        int oc = lin / 288, j = lin % 288;
        Wsm[oc * 292 + j] = g_wq2[lin];
    }
    if (t < 32) scmb[t] = g_comb2[t];
    __syncthreads();

    float m = 0.0f;
    if (t < 224) {
        int px = t % 56, ocg = t / 56;
        int acc[8];
        #pragma unroll
        for (int o = 0; o < 8; o++) acc[o] = 0;
        const int4* X4 = (const int4*)Xs;
        const int4* W4 = (const int4*)Wsm;
        #pragma unroll
        for (int tap = 0; tap < 9; tap++) {
            int cell4 = ((tap / 3) * 58 + px + tap % 3) * 9;   // *36/4
            #pragma unroll
            for (int kw4 = 0; kw4 < 8; kw4++) {
                int4 xv = X4[cell4 + kw4];
                #pragma unroll
                for (int o = 0; o < 8; o++) {
                    int4 wv = W4[(ocg * 8 + o) * 73 + tap * 8 + kw4];
                    int a = acc[o];
                    a = __dp4a(xv.x, wv.x, a);
                    a = __dp4a(xv.y, wv.y, a);
                    a = __dp4a(xv.z, wv.z, a);
                    a = __dp4a(xv.w, wv.w, a);
                    acc[o] = a;
                }
            }
        }
        #pragma unroll
        for (int o = 0; o < 8; o++) {
            int oc = ocg * 8 + o;
            float v = (float)acc[o] * scmb[oc];
            out[((b * 288) + 256 + oc) * HW + h * 56 + px] = v;
            m = fmaxf(m, fabsf(v));
        }
    }
    float bm = blockReduceMax(m);
    if (t == 0) atomicMax(&g_maxy, __float_as_uint(bm));
}

// ---------------- K8: s_out + tail ----------------
__global__ void k_scales_out(float* __restrict__ out, int out_size)
{
    float s = fmaxf(__uint_as_float(g_maxb), __uint_as_float(g_maxy)) / 127.0f + 1e-8f;
    if (threadIdx.x == 0) g_sout = s;
    for (int i = N_OUT + threadIdx.x; i < out_size; i += 32) out[i] = s;
}

// ---------------- K9a: requant batch -> out channels 0..255 ----------------
__global__ void k_out_batch(const float4* __restrict__ batch4, float4* __restrict__ out4)
{
    const int n4 = B_N * CIN * HW4;
    float s = g_sout, inv = 1.0f / s;
    for (int i = blockIdx.x * blockDim.x + threadIdx.x; i < n4;
         i += gridDim.x * blockDim.x) {
        int b = i / (CIN * HW4);
        int r = i - b * (CIN * HW4);
        float4 v = batch4[i];
        v.x = qclipf(rintf(v.x * inv), -128.0f, 127.0f) * s;
        v.y = qclipf(rintf(v.y * inv), -128.0f, 127.0f) * s;
        v.z = qclipf(rintf(v.z * inv), -128.0f, 127.0f) * s;
        v.w = qclipf(rintf(v.w * inv), -128.0f, 127.0f) * s;
        out4[b * (288 * HW4) + r] = v;
    }
}

// ---------------- K9b: requant y region in-place ----------------
__global__ void k_out_y(float4* __restrict__ out4)
{
    const int n4 = B_N * CO2 * HW4;
    float s = g_sout, inv = 1.0f / s;
    for (int i = blockIdx.x * blockDim.x + threadIdx.x; i < n4;
         i += gridDim.x * blockDim.x) {
        int b = i / (CO2 * HW4);
        int r = i - b * (CO2 * HW4);
        float4* p = out4 + b * (288 * HW4) + 256 * HW4 + r;
        float4 v = *p;
        v.x = qclipf(rintf(v.x * inv), -128.0f, 127.0f) * s;
        v.y = qclipf(rintf(v.y * inv), -128.0f, 127.0f) * s;
        v.z = qclipf(rintf(v.z * inv), -128.0f, 127.0f) * s;
        v.w = qclipf(rintf(v.w * inv), -128.0f, 127.0f) * s;
        *p = v;
    }
}

extern "C" void kernel_launch(void* const* d_in, const int* in_sizes, int n_in,
                              void* d_out, int out_size)
{
    const float* batch = (const float*)d_in[0];
    const float* s_in  = (const float*)d_in[1];
    const float* g1    = (const float*)d_in[2];
    const float* be1   = (const float*)d_in[3];
    const float* m1    = (const float*)d_in[4];
    const float* v1    = (const float*)d_in[5];
    const float* w1c   = (const float*)d_in[6];
    const float* g2    = (const float*)d_in[7];
    const float* be2   = (const float*)d_in[8];
    const float* m2    = (const float*)d_in[9];
    const float* v2    = (const float*)d_in[10];
    const float* w2c   = (const float*)d_in[11];
    float* out = (float*)d_out;

    static bool attr_done = false;
    if (!attr_done) {
        cudaFuncSetAttribute(k_conv1, cudaFuncAttributeMaxDynamicSharedMemorySize, 68096);
        cudaFuncSetAttribute(k_conv2, cudaFuncAttributeMaxDynamicSharedMemorySize, 62560);
        attr_done = true;
    }

    k_prep<<<3, 256>>>(g1, be1, m1, v1, s_in, w1c, g2, be2, m2, v2, w2c);
    k_max1<<<2048, 256>>>((const float4*)batch);
    k_scales1<<<1, 128>>>();
    k_quant1<<<PX / 64, 256>>>(batch);
    k_conv1<<<PX / 128, 256, 68096>>>();
    k_scales2<<<1, 32>>>();
    k_quant2<<<2048, 256>>>();
    k_conv2<<<dim3(56, 32), 256, 62560>>>(out);
    k_scales_out<<<1, 32>>>(out, out_size);
    k_out_batch<<<4096, 256>>>((const float4*)batch, (float4*)out);
    k_out_y<<<3136, 256>>>((float4*)out);
}

// round 4
// speedup vs baseline: 1.0697x; 1.0697x over previous
#include <cuda_runtime.h>
#include <cstdint>

#define B_N   32
#define CIN   256
#define HW    3136
#define HW4   784
#define PX    100352          // B_N*HW
#define CO1   128
#define CO2   32
#define N_OUT (32*288*3136)

// ---------------- scratch (device globals; no allocations) ----------------
__device__ float    g_w1q[CIN], g_b1q[CIN];
__device__ float    g_bf[CO1], g_sw1[CO1];
__device__ int      g_wq1t[64*CO1];         // int8 packed, [k=ci/4][oc]
__device__ float    g_sw2[CO2];
__device__ int      g_wq2[CO2*288];         // [oc][tap*32 + ci/4]
__device__ unsigned g_max1, g_max2, g_maxb, g_maxy;
__device__ float    g_x2[PX*CO1];           // conv1 out fp32 NHWC (51.4MB)
__device__ int      g_x2q32[PX*32];         // x2 codes NHWC packed (12.8MB)

// ---------------- helpers ----------------
__device__ __forceinline__ float warpMax(float v) {
    #pragma unroll
    for (int o = 16; o; o >>= 1) v = fmaxf(v, __shfl_xor_sync(0xffffffffu, v, o));
    return v;
}
__device__ __forceinline__ float blockReduceMax(float v) {
    __shared__ float sm[8];
    float w = warpMax(v);
    if ((threadIdx.x & 31) == 0) sm[threadIdx.x >> 5] = w;
    __syncthreads();
    float r = (threadIdx.x < (blockDim.x >> 5)) ? sm[threadIdx.x] : 0.0f;
    r = warpMax(r);
    __syncthreads();
    return r;  // valid in warp 0
}
__device__ __forceinline__ float qclipf(float q, float lo, float hi) {
    return fminf(fmaxf(q, lo), hi);
}

// ---------------- K0: weight prep ----------------
__global__ void k_prep(const float* __restrict__ g1, const float* __restrict__ be1,
                       const float* __restrict__ m1, const float* __restrict__ v1,
                       const float* __restrict__ s_in_p, const float* __restrict__ w1c,
                       const float* __restrict__ g2, const float* __restrict__ be2,
                       const float* __restrict__ m2, const float* __restrict__ v2,
                       const float* __restrict__ w2c)
{
    int t = threadIdx.x;
    if (blockIdx.x == 0) {
        if (t == 0) { g_max1 = 0u; g_max2 = 0u; g_maxb = 0u; g_maxy = 0u; }
        float w1 = g1[t] / sqrtf(v1[t] + 1e-5f);
        float b1 = be1[t] - m1[t] * w1;
        float bm = blockReduceMax(fabsf(w1));
        __shared__ float s_sbn;
        if (t == 0) s_sbn = bm / 127.0f + 1e-8f;
        __syncthreads();
        float sbn = s_sbn;
        float c = qclipf(rintf(w1 / sbn), -128.0f, 127.0f);
        g_w1q[t] = c * sbn;
        float sc = s_in_p[0] * sbn;
        g_b1q[t] = rintf(b1 / sc) * sc;
    } else if (blockIdx.x == 1) {
        if (t < CO1) {
            float tt = g2[t] / sqrtf(v2[t] + 1e-5f);
            const float* wr = w1c + t * CIN;
            float mx = 0.0f;
            for (int c = 0; c < CIN; c++) mx = fmaxf(mx, fabsf(wr[c] * tt));
            float s = mx / 127.0f + 1e-8f;
            g_sw1[t] = s;
            g_bf[t]  = be2[t] - m2[t] * tt;
            for (int cw = 0; cw < 64; cw++) {
                unsigned word = 0;
                #pragma unroll
                for (int j = 0; j < 4; j++) {
                    float wf = wr[cw * 4 + j] * tt;
                    int qi = (int)qclipf(rintf(wf / s), -128.0f, 127.0f);
                    word |= ((unsigned)(qi & 0xff)) << (8 * j);
                }
                g_wq1t[cw * CO1 + t] = (int)word;      // transposed [k][oc]
            }
        }
    } else {
        if (t < CO2) {
            const float* wr = w2c + t * 1152;   // [128 ci][3][3]
            float mx = 0.0f;
            for (int k = 0; k < 1152; k++) mx = fmaxf(mx, fabsf(wr[k]));
            float s = mx / 127.0f + 1e-8f;
            g_sw2[t] = s;
            for (int tap = 0; tap < 9; tap++)
                for (int cw = 0; cw < 32; cw++) {
                    unsigned word = 0;
                    #pragma unroll
                    for (int j = 0; j < 4; j++) {
                        int qi = (int)qclipf(rintf(wr[(cw * 4 + j) * 9 + tap] / s),
                                             -128.0f, 127.0f);
                        word |= ((unsigned)(qi & 0xff)) << (8 * j);
                    }
                    g_wq2[t * 288 + tap * 32 + cw] = (int)word;
                }
        }
    }
}

// ---------------- K1: max relu(bn1(batch)) and max|batch| ----------------
__global__ void k_max1(const float4* __restrict__ batch4)
{
    const int n4 = PX * CIN / 4;
    float m1 = 0.0f, mb = 0.0f;
    for (int i = blockIdx.x * blockDim.x + threadIdx.x; i < n4;
         i += gridDim.x * blockDim.x) {
        int c = (i / HW4) % CIN;
        float w = g_w1q[c], b = g_b1q[c];
        float4 v = batch4[i];
        m1 = fmaxf(m1, fmaxf(fmaf(v.x, w, b), 0.0f));
        m1 = fmaxf(m1, fmaxf(fmaf(v.y, w, b), 0.0f));
        m1 = fmaxf(m1, fmaxf(fmaf(v.z, w, b), 0.0f));
        m1 = fmaxf(m1, fmaxf(fmaf(v.w, w, b), 0.0f));
        mb = fmaxf(mb, fmaxf(fmaxf(fabsf(v.x), fabsf(v.y)),
                             fmaxf(fabsf(v.z), fabsf(v.w))));
    }
    float r1 = blockReduceMax(m1);
    if (threadIdx.x == 0) atomicMax(&g_max1, __float_as_uint(r1));
    float rb = blockReduceMax(mb);
    if (threadIdx.x == 0) atomicMax(&g_maxb, __float_as_uint(rb));
}

// ---- K2: fused bn1+quant+transpose + 1x1 int8 GEMM (128px x 128oc, K=256) ----
__global__ __launch_bounds__(256) void k_conv1(const float4* __restrict__ batch4)
{
    extern __shared__ int smem[];
    int* Ws = smem;                    // [64 k][132 oc-words]
    int* Bs = smem + 64 * 132;         // [64 k][132 px-words]
    float* sc1 = (float*)(Bs + 64 * 132);
    float* sb1 = sc1 + 128;
    unsigned char* Bs8 = (unsigned char*)Bs;
    int t = threadIdx.x;
    int p0 = blockIdx.x * 128;

    float sa1 = __uint_as_float(g_max1) / 127.0f + 1e-8f;
    float inv = 1.0f / sa1;
    if (t < 128) {
        float sc = sa1 * g_sw1[t];
        sc1[t] = sc;
        sb1[t] = rintf(g_bf[t] / sc) * sc;
    }

    // weights: 8192 words, conflict-free (consecutive oc)
    #pragma unroll
    for (int i = 0; i < 32; i++) {
        int lin = t + 256 * i;
        int k = lin >> 7, oc = lin & 127;
        Ws[k * 132 + oc] = g_wq1t[lin];
    }
    // activations: load batch NCHW, bn+relu+quantize, write bytes k-major
    #pragma unroll
    for (int i = 0; i < 32; i++) {
        int lin = t + 256 * i;                 // 8192 = 256ci x 32 groups
        int g = lin & 31, ci = lin >> 5;
        int pglob = p0 + 4 * g;
        int b = pglob / HW;
        int s = pglob - b * HW;
        float4 v = batch4[(b * CIN + ci) * HW4 + (s >> 2)];
        float w = g_w1q[ci], bb = g_b1q[ci];
        float x0 = fmaxf(fmaf(v.x, w, bb), 0.0f);
        float x1 = fmaxf(fmaf(v.y, w, bb), 0.0f);
        float x2 = fmaxf(fmaf(v.z, w, bb), 0.0f);
        float x3 = fmaxf(fmaf(v.w, w, bb), 0.0f);
        int k = ci >> 2, c3 = ci & 3;
        int base = (k * 132 + 4 * g) * 4 + c3;
        Bs8[base + 0]  = (unsigned char)(int)qclipf(rintf(x0 * inv), 0.0f, 127.0f);
        Bs8[base + 4]  = (unsigned char)(int)qclipf(rintf(x1 * inv), 0.0f, 127.0f);
        Bs8[base + 8]  = (unsigned char)(int)qclipf(rintf(x2 * inv), 0.0f, 127.0f);
        Bs8[base + 12] = (unsigned char)(int)qclipf(rintf(x3 * inv), 0.0f, 127.0f);
    }
    __syncthreads();

    int tx = t & 15, ty = t >> 4;              // tx: oc octet, ty: px octet
    int acc[64];
    #pragma unroll
    for (int i = 0; i < 64; i++) acc[i] = 0;
    const int* wp = Ws + 8 * tx;
    const int* bp = Bs + 8 * ty;
    #pragma unroll 2
    for (int k = 0; k < 64; k++) {
        int4 a0 = *(const int4*)(wp + k * 132);
        int4 a1 = *(const int4*)(wp + k * 132 + 4);
        int4 b0 = *(const int4*)(bp + k * 132);
        int4 b1 = *(const int4*)(bp + k * 132 + 4);
        int a[8] = {a0.x, a0.y, a0.z, a0.w, a1.x, a1.y, a1.z, a1.w};
        int bb[8] = {b0.x, b0.y, b0.z, b0.w, b1.x, b1.y, b1.z, b1.w};
        #pragma unroll
        for (int j = 0; j < 8; j++) {
            #pragma unroll
            for (int i2 = 0; i2 < 8; i2++)
                acc[j * 8 + i2] = __dp4a(bb[j], a[i2], acc[j * 8 + i2]);
        }
    }
    float m = 0.0f;
    #pragma unroll
    for (int j = 0; j < 8; j++) {
        int px = p0 + ty * 8 + j;
        float vals[8];
        #pragma unroll
        for (int i2 = 0; i2 < 8; i2++) {
            int oc = tx * 8 + i2;
            float v = fmaxf(fmaf((float)acc[j * 8 + i2], sc1[oc], sb1[oc]), 0.0f);
            vals[i2] = v; m = fmaxf(m, v);
        }
        float4* op = (float4*)&g_x2[px * 128 + tx * 8];
        op[0] = make_float4(vals[0], vals[1], vals[2], vals[3]);
        op[1] = make_float4(vals[4], vals[5], vals[6], vals[7]);
    }
    float bm = blockReduceMax(m);
    if (t == 0) atomicMax(&g_max2, __float_as_uint(bm));
}

// ---------------- K3: quantize x2 (fp32) -> int8 NHWC packed ----------------
__global__ void k_quant2()
{
    const int n = PX * 32;
    float inv = 1.0f / (__uint_as_float(g_max2) / 127.0f + 1e-8f);
    const float4* xp = (const float4*)g_x2;
    for (int i = blockIdx.x * blockDim.x + threadIdx.x; i < n;
         i += gridDim.x * blockDim.x) {
        float4 v = xp[i];
        int q0 = (int)qclipf(rintf(v.x * inv), 0.0f, 127.0f);
        int q1 = (int)qclipf(rintf(v.y * inv), 0.0f, 127.0f);
        int q2 = (int)qclipf(rintf(v.z * inv), 0.0f, 127.0f);
        int q3 = (int)qclipf(rintf(v.w * inv), 0.0f, 127.0f);
        g_x2q32[i] = q0 | (q1 << 8) | (q2 << 16) | (q3 << 24);
    }
}

// ---------------- K4: conv2 3x3 int8, 4 rows per block ----------------
__global__ __launch_bounds__(256) void k_conv2(float* __restrict__ out)
{
    extern __shared__ int smem[];
    int*   Xs   = smem;                    // [6 rows][58 cols] cells of 36 words
    int*   Wsm  = smem + 6 * 58 * 36;      // [32 oc][292]
    float* scmb = (float*)(Wsm + 32 * 292);
    int t = threadIdx.x;
    int h0 = blockIdx.x * 4, b = blockIdx.y;

    float sa2 = __uint_as_float(g_max2) / 127.0f + 1e-8f;
    if (t < 32) scmb[t] = sa2 * g_sw2[t];

    for (int lin = t; lin < 6 * 58 * 32; lin += 256) {
        int row = lin / (58 * 32);
        int rem = lin - row * (58 * 32);
        int col = rem >> 5, kw = rem & 31;
        int hh = h0 + row - 1;
        int val = 0;
        if (col >= 1 && col <= 56 && hh >= 0 && hh <= 55)
            val = g_x2q32[((b * HW) + hh * 56 + (col - 1)) * 32 + kw];
        Xs[(row * 58 + col) * 36 + kw] = val;
    }
    for (int lin = t; lin < 32 * 288; lin += 256) {
        int oc = lin / 288, j = lin - oc * 288;
        Wsm[oc * 292 + j] = g_wq2[lin];
    }
    __syncthreads();

    float m = 0.0f;
    if (t < 224) {
        int px = t % 56, ocg = t / 56;
        int acc[32];                       // [h][oc]
        #pragma unroll
        for (int i = 0; i < 32; i++) acc[i] = 0;
        const int4* X4 = (const int4*)Xs;
        const int4* W4 = (const int4*)Wsm + (ocg * 8) * 73;
        #pragma unroll 1
        for (int tap = 0; tap < 9; tap++) {
            int base = ((tap / 3) * 58 + px + tap % 3) * 9;
            const int4* w4 = W4 + tap * 8;
            #pragma unroll 2
            for (int kw4 = 0; kw4 < 8; kw4++) {
                int4 xv0 = X4[base + kw4];
                int4 xv1 = X4[base + 522 + kw4];
                int4 xv2 = X4[base + 1044 + kw4];
                int4 xv3 = X4[base + 1566 + kw4];
                #pragma unroll
                for (int o = 0; o < 8; o++) {
                    int4 wv = w4[o * 73 + kw4];
                    int a0 = acc[o], a1 = acc[8 + o], a2 = acc[16 + o], a3 = acc[24 + o];
                    a0 = __dp4a(xv0.x, wv.x, a0); a0 = __dp4a(xv0.y, wv.y, a0);
                    a0 = __dp4a(xv0.z, wv.z, a0); a0 = __dp4a(xv0.w, wv.w, a0);
                    a1 = __dp4a(xv1.x, wv.x, a1); a1 = __dp4a(xv1.y, wv.y, a1);
                    a1 = __dp4a(xv1.z, wv.z, a1); a1 = __dp4a(xv1.w, wv.w, a1);
                    a2 = __dp4a(xv2.x, wv.x, a2); a2 = __dp4a(xv2.y, wv.y, a2);
                    a2 = __dp4a(xv2.z, wv.z, a2); a2 = __dp4a(xv2.w, wv.w, a2);
                    a3 = __dp4a(xv3.x, wv.x, a3); a3 = __dp4a(xv3.y, wv.y, a3);
                    a3 = __dp4a(xv3.z, wv.z, a3); a3 = __dp4a(xv3.w, wv.w, a3);
                    acc[o] = a0; acc[8 + o] = a1; acc[16 + o] = a2; acc[24 + o] = a3;
                }
            }
        }
        #pragma unroll
        for (int hh = 0; hh < 4; hh++) {
            #pragma unroll
            for (int o = 0; o < 8; o++) {
                int oc = ocg * 8 + o;
                float v = (float)acc[hh * 8 + o] * scmb[oc];
                out[((b * 288) + 256 + oc) * HW + (h0 + hh) * 56 + px] = v;
                m = fmaxf(m, fabsf(v));
            }
        }
    }
    float bm = blockReduceMax(m);
    if (t == 0) atomicMax(&g_maxy, __float_as_uint(bm));
}

// ---------------- K5: output requant (batch region + y region + tail) --------
__global__ void k_out(const float4* __restrict__ batch4, float4* __restrict__ out4,
                      float* __restrict__ out, int out_size)
{
    const int n4b = B_N * CIN * HW4;       // 6422528
    const int n4y = B_N * CO2 * HW4;       // 802816
    float s = fmaxf(__uint_as_float(g_maxb), __uint_as_float(g_maxy)) / 127.0f + 1e-8f;
    float inv = 1.0f / s;
    int i = blockIdx.x * blockDim.x + threadIdx.x;
    if (i < n4b) {
        int b = i / (CIN * HW4);
        int r = i - b * (CIN * HW4);
        float4 v = batch4[i];
        v.x = qclipf(rintf(v.x * inv), -128.0f, 127.0f) * s;
        v.y = qclipf(rintf(v.y * inv), -128.0f, 127.0f) * s;
        v.z = qclipf(rintf(v.z * inv), -128.0f, 127.0f) * s;
        v.w = qclipf(rintf(v.w * inv), -128.0f, 127.0f) * s;
        out4[b * (288 * HW4) + r] = v;
    } else if (i < n4b + n4y) {
        int j = i - n4b;
        int b = j / (CO2 * HW4);
        int r = j - b * (CO2 * HW4);
        float4* p = out4 + b * (288 * HW4) + 256 * HW4 + r;
        float4 v = *p;
        v.x = qclipf(rintf(v.x * inv), -128.0f, 127.0f) * s;
        v.y = qclipf(rintf(v.y * inv), -128.0f, 127.0f) * s;
        v.z = qclipf(rintf(v.z * inv), -128.0f, 127.0f) * s;
        v.w = qclipf(rintf(v.w * inv), -128.0f, 127.0f) * s;
        *p = v;
    }
    if (blockIdx.x == 0 && threadIdx.x == 0)
        for (int k = N_OUT; k < out_size; k++) out[k] = s;
}

extern "C" void kernel_launch(void* const* d_in, const int* in_sizes, int n_in,
                              void* d_out, int out_size)
{
    const float* batch = (const float*)d_in[0];
    const float* s_in  = (const float*)d_in[1];
    const float* g1    = (const float*)d_in[2];
    const float* be1   = (const float*)d_in[3];
    const float* m1    = (const float*)d_in[4];
    const float* v1    = (const float*)d_in[5];
    const float* w1c   = (const float*)d_in[6];
    const float* g2    = (const float*)d_in[7];
    const float* be2   = (const float*)d_in[8];
    const float* m2    = (const float*)d_in[9];
    const float* v2    = (const float*)d_in[10];
    const float* w2c   = (const float*)d_in[11];
    float* out = (float*)d_out;

    static bool attr_done = false;
    if (!attr_done) {
        cudaFuncSetAttribute(k_conv1, cudaFuncAttributeMaxDynamicSharedMemorySize, 68608);
        cudaFuncSetAttribute(k_conv2, cudaFuncAttributeMaxDynamicSharedMemorySize, 87616);
        attr_done = true;
    }

    k_prep<<<3, 256>>>(g1, be1, m1, v1, s_in, w1c, g2, be2, m2, v2, w2c);
    k_max1<<<2048, 256>>>((const float4*)batch);
    k_conv1<<<PX / 128, 256, 68608>>>((const float4*)batch);
    k_quant2<<<2048, 256>>>();
    k_conv2<<<dim3(14, 32), 256, 87616>>>(out);
    k_out<<<(B_N * (CIN + CO2) * HW4 + 255) / 256, 256>>>(
        (const float4*)batch, (float4*)out, out, out_size);
}